// round 1
// baseline (speedup 1.0000x reference)
#include <cuda_runtime.h>
#include <cstdint>

#define NTHREADS 512
#define NWARPS   16
#define KC       32
#define DD       64
#define CPAD     36          // padded row stride (floats): conflict-free LDS.128
#define MAX_M    1520        // max samples per graph held in SMEM (380 nodes)
#define ITERS    50
#define INV_EPS  10.0f       // 1/0.1

// SMEM layout (floats): c[MAX_M*CPAD] | cbT[64*32] | cbn[32] | Gs[32] | Wpart[16*32] | rng[2 ints]
#define SMEM_FLOATS (MAX_M*CPAD + DD*KC + KC + KC + NWARPS*KC)
#define SMEM_BYTES  (SMEM_FLOATS*4 + 16)

// Fallback scratch for graphs too large for SMEM (statically allocated — allowed).
// Sized for full M = 100000*4 samples * 32 columns.
__device__ float g_cscratch[12800000u];

__device__ __forceinline__ float warpAllSum(float v) {
#pragma unroll
    for (int off = 16; off; off >>= 1) v += __shfl_xor_sync(0xffffffffu, v, off);
    return v;
}

__device__ __forceinline__ int lower_bound_dev(const int* __restrict__ a, int n, int key) {
    int lo = 0, hi = n;
    while (lo < hi) {
        int mid = (lo + hi) >> 1;
        if (__ldg(a + mid) < key) lo = mid + 1; else hi = mid;
    }
    return lo;
}

extern "C" __global__ void __launch_bounds__(NTHREADS, 1)
sinkhorn_hist_kernel(const float* __restrict__ X, const float* __restrict__ cb,
                     const int* __restrict__ bidx, float* __restrict__ out,
                     int N, int S) {
    extern __shared__ float sm[];
    float* csm   = sm;
    float* cbT   = sm + MAX_M * CPAD;        // [d][j] transposed codebook
    float* cbn   = cbT + DD * KC;            // ||cb_j||^2
    float* Gs    = cbn + KC;                 // dual G (g/eps)
    float* Wpart = Gs + KC;                  // per-warp partial column sums
    int*   rng   = (int*)(Wpart + NWARPS * KC);

    const int b    = blockIdx.x;
    const int tid  = threadIdx.x;
    const int lane = tid & 31;
    const int warp = tid >> 5;

    if (tid == 0) {
        rng[0] = lower_bound_dev(bidx, N, b);
        rng[1] = lower_bound_dev(bidx, N, b + 1);
    }
    // Stage codebook transposed + norms; init duals.
    for (int idx = tid; idx < KC * DD; idx += NTHREADS) {
        int d = idx >> 5, j = idx & 31;
        cbT[idx] = cb[j * DD + d];
    }
    if (tid < KC) {
        float s = 0.f;
#pragma unroll
        for (int d = 0; d < DD; d++) { float v = cb[tid * DD + d]; s = fmaf(v, v, s); }
        cbn[tid] = s;
        Gs[tid]  = 0.f;
    }
    __syncthreads();

    const int lo = rng[0];
    const int n  = rng[1] - rng[0];
    const int m  = n * S;

    if (n == 0) {                       // empty graph -> uniform
        if (tid < KC) out[b * KC + tid] = 1.0f / KC;
        return;
    }

    const bool insm    = (m <= MAX_M);
    float*     cbase   = insm ? csm : (g_cscratch + (size_t)lo * S * KC);
    const int  cstride = insm ? CPAD : KC;

    // ---- Phase A: scaled cost rows c_ij = max(||x||^2+||cb_j||^2-2 x.cb_j, 0)/eps ----
    // warp-per-sample: lane j computes c_{s,j}; x broadcast via shfl, cbT read conflict-free.
    for (int s = warp; s < m; s += NWARPS) {
        const float* xr = X + (size_t)(lo * S + s) * DD;
        float xa = xr[lane];
        float xb = xr[lane + 32];
        float nrm = warpAllSum(fmaf(xa, xa, xb * xb));
        float acc = 0.f;
#pragma unroll
        for (int d = 0; d < 32; d++)
            acc = fmaf(__shfl_sync(0xffffffffu, xa, d), cbT[d * 32 + lane], acc);
#pragma unroll
        for (int d = 0; d < 32; d++)
            acc = fmaf(__shfl_sync(0xffffffffu, xb, d), cbT[(d + 32) * 32 + lane], acc);
        float cost = fmaxf(fmaf(-2.f, acc, nrm + cbn[lane]), 0.f);
        cbase[(size_t)s * cstride + lane] = cost * INV_EPS;
    }
    __syncthreads();

    const float log_mK = logf((float)m * (1.f / KC));
    const float inv_m  = 1.f / (float)m;

    // ---- Phase B: 50 Sinkhorn passes + 1 histogram pass ----
    // Per pass, per sample: t_j = G_j - c_ij; w = softmax_j(t); A_j += w_j.
    // G update: G_j += log(m/K) - log(sum_i w_ij). Final pass: hist = W / sum(W).
    for (int pass = 0; pass <= ITERS; pass++) {
        float Greg[KC];
#pragma unroll
        for (int q = 0; q < KC / 4; q++) {
            float4 g4 = reinterpret_cast<const float4*>(Gs)[q];
            Greg[4*q] = g4.x; Greg[4*q+1] = g4.y; Greg[4*q+2] = g4.z; Greg[4*q+3] = g4.w;
        }
        float A[KC];
#pragma unroll
        for (int j = 0; j < KC; j++) A[j] = 0.f;

        for (int s = tid; s < m; s += NTHREADS) {
            const float4* r4 = reinterpret_cast<const float4*>(cbase + (size_t)s * cstride);
            float t[KC];
#pragma unroll
            for (int q = 0; q < 8; q++) {
                float4 v = r4[q];
                t[4*q]   = Greg[4*q]   - v.x;
                t[4*q+1] = Greg[4*q+1] - v.y;
                t[4*q+2] = Greg[4*q+2] - v.z;
                t[4*q+3] = Greg[4*q+3] - v.w;
            }
            // max via 4 independent chains (shorter dep chains)
            float m0 = t[0], m1 = t[1], m2 = t[2], m3 = t[3];
#pragma unroll
            for (int j = 4; j < KC; j += 4) {
                m0 = fmaxf(m0, t[j]);
                m1 = fmaxf(m1, t[j+1]);
                m2 = fmaxf(m2, t[j+2]);
                m3 = fmaxf(m3, t[j+3]);
            }
            float mx = fmaxf(fmaxf(m0, m1), fmaxf(m2, m3));
            float s0 = 0.f, s1 = 0.f, s2 = 0.f, s3 = 0.f;
#pragma unroll
            for (int j = 0; j < KC; j += 4) {
                float e0 = __expf(t[j]   - mx);
                float e1 = __expf(t[j+1] - mx);
                float e2 = __expf(t[j+2] - mx);
                float e3 = __expf(t[j+3] - mx);
                t[j] = e0; t[j+1] = e1; t[j+2] = e2; t[j+3] = e3;
                s0 += e0; s1 += e1; s2 += e2; s3 += e3;
            }
            float inv = __fdividef(1.f, (s0 + s1) + (s2 + s3));
#pragma unroll
            for (int j = 0; j < KC; j++) A[j] = fmaf(t[j], inv, A[j]);
        }

        // butterfly reduce A[] across the warp
#pragma unroll
        for (int off = 16; off; off >>= 1)
#pragma unroll
            for (int j = 0; j < KC; j++)
                A[j] += __shfl_xor_sync(0xffffffffu, A[j], off);
        if (lane == 0) {
#pragma unroll
            for (int j = 0; j < KC; j++) Wpart[warp * KC + j] = A[j];
        }
        __syncthreads();

        if (tid < KC) {
            float w = 0.f;
#pragma unroll
            for (int k = 0; k < NWARPS; k++) w += Wpart[k * KC + tid];
            if (pass < ITERS) {
                w = fmaxf(w, 1e-38f);
                Gs[tid] = Gs[tid] + log_mK - logf(w);
            } else {
                float u = w * inv_m;                    // exp(segLSE(log_pi))_j = a * W_j
                float ssum = warpAllSum(u) + 1e-12f;
                out[b * KC + tid] = u / ssum;
            }
        }
        __syncthreads();
    }
}

extern "C" void kernel_launch(void* const* d_in, const int* in_sizes, int n_in,
                              void* d_out, int out_size) {
    const float* X    = (const float*)d_in[0];
    const float* cb   = (const float*)d_in[1];
    const int*   bidx = (const int*)d_in[2];
    float*       out  = (float*)d_out;

    int N = in_sizes[2];                 // number of nodes
    int S = in_sizes[0] / (N * DD);      // samples per node (4)
    int B = out_size / KC;               // number of graphs (512)

    cudaFuncSetAttribute(sinkhorn_hist_kernel,
                         cudaFuncAttributeMaxDynamicSharedMemorySize, SMEM_BYTES);
    sinkhorn_hist_kernel<<<B, NTHREADS, SMEM_BYTES>>>(X, cb, bidx, out, N, S);
}

// round 3
// speedup vs baseline: 1.4499x; 1.4499x over previous
#include <cuda_runtime.h>
#include <cstdint>

#define NTHREADS 512
#define NWARPS   16
#define KC       32
#define DD       64
#define CPAD     36            // padded row stride (floats): conflict-free LDS.128
#define MAX_M    1530          // rows held in SMEM (covers mean+>20 sigma)
#define ITERS    50
// s = (1/eps)*log2(e) = 10 * 1.4426950408889634
#define SLOG2    14.426950408889634f
#define S2LOG2   28.853900817779268f

// SMEM (floats): rows[MAX_M*36] | cbS[32*64] | sB[32] | Gs[32] | Wpart[16*32] | rng
#define ROWS_F   (MAX_M*CPAD)
#define SMEM_FLOATS (ROWS_F + KC*DD + KC + KC + NWARPS*KC + 8)
#define SMEM_BYTES  (SMEM_FLOATS*4)

// DRAM fallback scratch (400000 samples * 32 cols) — statically allocated.
__device__ float g_cscratch[12800000u];

__device__ __forceinline__ float ex2f(float x) {
    float y; asm("ex2.approx.ftz.f32 %0, %1;" : "=f"(y) : "f"(x)); return y;
}
__device__ __forceinline__ float rcpf(float x) {
    float y; asm("rcp.approx.ftz.f32 %0, %1;" : "=f"(y) : "f"(x)); return y;
}
__device__ __forceinline__ float warpAllSum(float v) {
#pragma unroll
    for (int off = 16; off; off >>= 1) v += __shfl_xor_sync(0xffffffffu, v, off);
    return v;
}
__device__ __forceinline__ int lower_bound_dev(const int* __restrict__ a, int n, int key) {
    int lo = 0, hi = n;
    while (lo < hi) { int mid = (lo + hi) >> 1; if (__ldg(a + mid) < key) lo = mid + 1; else hi = mid; }
    return lo;
}

extern "C" __global__ void __launch_bounds__(NTHREADS, 1)
sinkhorn_hist_kernel(const float* __restrict__ X, const float* __restrict__ cb,
                     const int* __restrict__ bidx, float* __restrict__ out,
                     int N, int S) {
    extern __shared__ float sm[];
    float* smrows = sm;                       // [MAX_M][36]
    float* cbS    = sm + ROWS_F;              // [32][64] row-major
    float* sB     = cbS + KC * DD;            // s*||cb_j||^2
    float* Gs     = sB + KC;                  // duals (log2 domain)
    float* Wpart  = Gs + KC;                  // [16][32]
    int*   rng    = (int*)(Wpart + NWARPS * KC);

    const int b    = blockIdx.x;
    const int tid  = threadIdx.x;
    const int lane = tid & 31;
    const int warp = tid >> 5;

    if (tid == 0) {
        rng[0] = lower_bound_dev(bidx, N, b);
        rng[1] = lower_bound_dev(bidx, N, b + 1);
    }
    // stage codebook (row-major, broadcast-read later)
    for (int i = tid; i < KC * DD; i += NTHREADS) cbS[i] = __ldg(cb + i);
    if (tid < KC) {
        float s = 0.f;
#pragma unroll
        for (int d = 0; d < DD; d++) { float v = __ldg(cb + tid * DD + d); s = fmaf(v, v, s); }
        sB[tid] = SLOG2 * s;
        Gs[tid] = 0.f;
    }
    __syncthreads();

    const int lo = rng[0];
    const int n  = rng[1] - rng[0];
    const int m  = n * S;

    if (n == 0) { if (tid < KC) out[b * KC + tid] = 1.0f / KC; return; }

    const bool insm = (m <= MAX_M);
    float* grow_base = g_cscratch + (size_t)(lo * S) * KC;

    // ---------------- Phase A: r_ij = s*(v_j - vmax_i), v_j = 2s*(x.cb_j) - s*||cb_j||^2
    // (||x||^2 and the max(.,0) clamp are per-row constants -> cancel in every
    //  softmax / LSE of the algorithm, so they are dropped entirely)
    for (int s0 = tid; s0 < m; s0 += NTHREADS) {
        const float4* xr = (const float4*)(X + ((size_t)(lo * S + s0) << 6));
        float4 x4[16];
#pragma unroll
        for (int i = 0; i < 16; i++) x4[i] = __ldg(xr + i);
        float v[KC];
#pragma unroll
        for (int j = 0; j < KC; j++) {
            const float4* cbr = (const float4*)&cbS[j * DD];
            float a0 = 0.f, a1 = 0.f, a2 = 0.f, a3 = 0.f;
#pragma unroll
            for (int q = 0; q < 16; q++) {
                float4 c4 = cbr[q];
                a0 = fmaf(x4[q].x, c4.x, a0);
                a1 = fmaf(x4[q].y, c4.y, a1);
                a2 = fmaf(x4[q].z, c4.z, a2);
                a3 = fmaf(x4[q].w, c4.w, a3);
            }
            v[j] = fmaf(S2LOG2, (a0 + a1) + (a2 + a3), -sB[j]);
        }
        float m0 = v[0], m1 = v[1], m2 = v[2], m3 = v[3];
#pragma unroll
        for (int j = 4; j < KC; j += 4) {
            m0 = fmaxf(m0, v[j]);   m1 = fmaxf(m1, v[j+1]);
            m2 = fmaxf(m2, v[j+2]); m3 = fmaxf(m3, v[j+3]);
        }
        float vmax = fmaxf(fmaxf(m0, m1), fmaxf(m2, m3));
        if (insm) {
#pragma unroll
            for (int q = 0; q < 8; q++)
                *(float4*)&smrows[s0 * CPAD + 4 * q] =
                    make_float4(v[4*q]-vmax, v[4*q+1]-vmax, v[4*q+2]-vmax, v[4*q+3]-vmax);
        } else {
            float4* gr = (float4*)(grow_base + (size_t)s0 * KC);
#pragma unroll
            for (int q = 0; q < 8; q++)
                gr[q] = make_float4(v[4*q]-vmax, v[4*q+1]-vmax, v[4*q+2]-vmax, v[4*q+3]-vmax);
        }
    }
    __syncthreads();

    const float log2_mK = __log2f((float)m * (1.0f / KC));
    const float inv_m   = 1.0f / (float)m;

    // ---------------- Phase B: 50 Sinkhorn passes + 1 histogram pass
    // Per sample: t_j = G_j + r_ij; w = softmax_j(t); A_j += w_j.
    // G update: G_j += log2(m/K) - log2(sum_i w_ij). Final: hist = W / sum(W).
#define PASS_LOOP(LOADR)                                                        \
    for (int pass = 0; pass <= ITERS; pass++) {                                 \
        float A[KC];                                                            \
        _Pragma("unroll") for (int j = 0; j < KC; j++) A[j] = 0.f;              \
        for (int base = 0; base < m; base += 2 * NTHREADS) {                    \
            int sA = base + tid, sBn = base + tid + NTHREADS;                   \
            int iA = (sA < m) ? sA : 0, iB = (sBn < m) ? sBn : 0;               \
            float tA[KC], tB[KC];                                               \
            _Pragma("unroll") for (int q = 0; q < 8; q++) {                     \
                float4 g4 = *(const float4*)&Gs[4 * q];                         \
                float4 a4 = LOADR(iA, q);                                       \
                float4 b4 = LOADR(iB, q);                                       \
                tA[4*q]   = g4.x + a4.x; tA[4*q+1] = g4.y + a4.y;               \
                tA[4*q+2] = g4.z + a4.z; tA[4*q+3] = g4.w + a4.w;               \
                tB[4*q]   = g4.x + b4.x; tB[4*q+1] = g4.y + b4.y;               \
                tB[4*q+2] = g4.z + b4.z; tB[4*q+3] = g4.w + b4.w;               \
            }                                                                   \
            float a0 = tA[0], a1 = tA[1], a2 = tA[2], a3 = tA[3];               \
            float b0 = tB[0], b1 = tB[1], b2 = tB[2], b3 = tB[3];               \
            _Pragma("unroll") for (int j = 4; j < KC; j += 4) {                 \
                a0 = fmaxf(a0, tA[j]);   a1 = fmaxf(a1, tA[j+1]);               \
                a2 = fmaxf(a2, tA[j+2]); a3 = fmaxf(a3, tA[j+3]);               \
                b0 = fmaxf(b0, tB[j]);   b1 = fmaxf(b1, tB[j+1]);               \
                b2 = fmaxf(b2, tB[j+2]); b3 = fmaxf(b3, tB[j+3]);               \
            }                                                                   \
            float mxA = fmaxf(fmaxf(a0, a1), fmaxf(a2, a3));                    \
            float mxB = fmaxf(fmaxf(b0, b1), fmaxf(b2, b3));                    \
            float sA0 = 0.f, sA1 = 0.f, sA2 = 0.f, sA3 = 0.f;                   \
            float sB0 = 0.f, sB1 = 0.f, sB2 = 0.f, sB3 = 0.f;                   \
            _Pragma("unroll") for (int j = 0; j < KC; j += 4) {                 \
                float eA0 = ex2f(tA[j] - mxA),   eA1 = ex2f(tA[j+1] - mxA);     \
                float eA2 = ex2f(tA[j+2] - mxA), eA3 = ex2f(tA[j+3] - mxA);     \
                float eB0 = ex2f(tB[j] - mxB),   eB1 = ex2f(tB[j+1] - mxB);     \
                float eB2 = ex2f(tB[j+2] - mxB), eB3 = ex2f(tB[j+3] - mxB);     \
                tA[j] = eA0; tA[j+1] = eA1; tA[j+2] = eA2; tA[j+3] = eA3;       \
                tB[j] = eB0; tB[j+1] = eB1; tB[j+2] = eB2; tB[j+3] = eB3;       \
                sA0 += eA0; sA1 += eA1; sA2 += eA2; sA3 += eA3;                 \
                sB0 += eB0; sB1 += eB1; sB2 += eB2; sB3 += eB3;                 \
            }                                                                   \
            float invA = rcpf((sA0 + sA1) + (sA2 + sA3));                       \
            float invB = rcpf((sB0 + sB1) + (sB2 + sB3));                       \
            invA = (sA  < m) ? invA : 0.f;                                      \
            invB = (sBn < m) ? invB : 0.f;                                      \
            _Pragma("unroll") for (int j = 0; j < KC; j++) {                    \
                A[j] = fmaf(tA[j], invA, A[j]);                                 \
                A[j] = fmaf(tB[j], invB, A[j]);                                 \
            }                                                                   \
        }                                                                       \
        /* tree-halving cross-lane reduce: lane l ends with column-l sum */     \
        _Pragma("unroll") for (int off = 16; off; off >>= 1) {                  \
            bool hi = (lane & off) != 0;                                        \
            _Pragma("unroll") for (int i = 0; i < off; i++) {                   \
                float send = hi ? A[i] : A[i + off];                            \
                float recv = __shfl_xor_sync(0xffffffffu, send, off);           \
                float keep = hi ? A[i + off] : A[i];                            \
                A[i] = keep + recv;                                             \
            }                                                                   \
        }                                                                       \
        Wpart[warp * KC + lane] = A[0];                                         \
        __syncthreads();                                                        \
        if (warp == 0) {                                                        \
            float w = 0.f;                                                      \
            _Pragma("unroll") for (int k = 0; k < NWARPS; k++)                  \
                w += Wpart[k * KC + lane];                                      \
            if (pass < ITERS) {                                                 \
                Gs[lane] = Gs[lane] + log2_mK - __log2f(fmaxf(w, 1e-38f));      \
            } else {                                                            \
                float u = w * inv_m;                                            \
                float ssum = warpAllSum(u) + 1e-12f;                            \
                out[b * KC + lane] = u / ssum;                                  \
            }                                                                   \
        }                                                                       \
        __syncthreads();                                                        \
    }

#define LOADR_S(ii, q) (*(const float4*)&smrows[(ii) * CPAD + 4 * (q)])
#define LOADR_G(ii, q) (__ldg((const float4*)(grow_base + (size_t)(ii) * KC) + (q)))

    if (insm) {
        PASS_LOOP(LOADR_S)
    } else {
        PASS_LOOP(LOADR_G)
    }
#undef PASS_LOOP
#undef LOADR_S
#undef LOADR_G
}

extern "C" void kernel_launch(void* const* d_in, const int* in_sizes, int n_in,
                              void* d_out, int out_size) {
    const float* X    = (const float*)d_in[0];
    const float* cb   = (const float*)d_in[1];
    const int*   bidx = (const int*)d_in[2];
    float*       out  = (float*)d_out;

    int N = in_sizes[2];
    int S = in_sizes[0] / (N * DD);
    int B = out_size / KC;

    cudaFuncSetAttribute(sinkhorn_hist_kernel,
                         cudaFuncAttributeMaxDynamicSharedMemorySize, SMEM_BYTES);
    sinkhorn_hist_kernel<<<B, NTHREADS, SMEM_BYTES>>>(X, cb, bidx, out, N, S);
}

// round 4
// speedup vs baseline: 1.5900x; 1.0967x over previous
#include <cuda_runtime.h>
#include <cstdint>

#define NTHREADS 512
#define NWARPS   16
#define KC       32
#define DD       64
#define CPAD     36            // padded row stride (floats): conflict-free LDS.128
#define MAX_M    1520          // rows held in SMEM (mean 781, sigma ~56 -> +13 sigma)
#define ITERS    50
// s = (1/eps)*log2(e) = 10 * 1.4426950408889634
#define SLOG2    14.426950408889634f
#define S2LOG2   28.853900817779268f

// SMEM (floats): rows[MAX_M*36] | cbS[32*64] | sB[32] | Gs[32] | Wp[2][16][32] | rng
#define ROWS_F   (MAX_M*CPAD)
#define SMEM_FLOATS (ROWS_F + KC*DD + KC + KC + 2*NWARPS*KC + 8)
#define SMEM_BYTES  (SMEM_FLOATS*4)

// DRAM fallback scratch (400000 samples * 32 cols) — statically allocated.
__device__ float g_cscratch[12800000u];

__device__ __forceinline__ float ex2f(float x) {
    float y; asm("ex2.approx.ftz.f32 %0, %1;" : "=f"(y) : "f"(x)); return y;
}
__device__ __forceinline__ float rcpf(float x) {
    float y; asm("rcp.approx.ftz.f32 %0, %1;" : "=f"(y) : "f"(x)); return y;
}
__device__ __forceinline__ float warpAllSum(float v) {
#pragma unroll
    for (int off = 16; off; off >>= 1) v += __shfl_xor_sync(0xffffffffu, v, off);
    return v;
}
__device__ __forceinline__ int lower_bound_dev(const int* __restrict__ a, int n, int key) {
    int lo = 0, hi = n;
    while (lo < hi) { int mid = (lo + hi) >> 1; if (__ldg(a + mid) < key) lo = mid + 1; else hi = mid; }
    return lo;
}

extern "C" __global__ void __launch_bounds__(NTHREADS, 1)
sinkhorn_hist_kernel(const float* __restrict__ X, const float* __restrict__ cb,
                     const int* __restrict__ bidx, float* __restrict__ out,
                     int N, int S) {
    extern __shared__ float sm[];
    float* smrows = sm;                       // [MAX_M][36]
    float* cbS    = sm + ROWS_F;              // [32][64]
    float* sB     = cbS + KC * DD;            // s*||cb_j||^2
    float* Gs     = sB + KC;                  // duals (log2 domain)
    float* Wp     = Gs + KC;                  // [2][16][32] double-buffered partials
    int*   rng    = (int*)(Wp + 2 * NWARPS * KC);

    const int b    = blockIdx.x;
    const int tid  = threadIdx.x;
    const int lane = tid & 31;
    const int warp = tid >> 5;

    if (tid == 0) {
        rng[0] = lower_bound_dev(bidx, N, b);
        rng[1] = lower_bound_dev(bidx, N, b + 1);
    }
    for (int i = tid; i < KC * DD; i += NTHREADS) cbS[i] = __ldg(cb + i);
    if (tid < KC) {
        float s = 0.f;
#pragma unroll
        for (int d = 0; d < DD; d++) { float v = __ldg(cb + tid * DD + d); s = fmaf(v, v, s); }
        sB[tid] = SLOG2 * s;
        Gs[tid] = 0.f;
    }
    __syncthreads();

    const int lo = rng[0];
    const int n  = rng[1] - rng[0];
    const int m  = n * S;

    if (n == 0) { if (tid < KC) out[b * KC + tid] = 1.0f / KC; return; }

    const bool insm = (m <= MAX_M);
    float* grow_base = g_cscratch + (size_t)(lo * S) * KC;

    // ---------------- Phase A: r_ij = s*(v_j - vmax_i), v_j = 2s*(x.cb_j) - s*||cb_j||^2
    // (||x||^2 and the max(.,0) clamp are per-row constants -> cancel in every
    //  softmax / LSE of the algorithm, so they are dropped entirely)
    for (int s0 = tid; s0 < m; s0 += NTHREADS) {
        const float4* xr = (const float4*)(X + ((size_t)(lo * S + s0) << 6));
        float4 x4[16];
#pragma unroll
        for (int i = 0; i < 16; i++) x4[i] = __ldg(xr + i);
        float v[KC];
#pragma unroll
        for (int j = 0; j < KC; j++) {
            const float4* cbr = (const float4*)&cbS[j * DD];
            float a0 = 0.f, a1 = 0.f, a2 = 0.f, a3 = 0.f;
#pragma unroll
            for (int q = 0; q < 16; q++) {
                float4 c4 = cbr[q];
                a0 = fmaf(x4[q].x, c4.x, a0);
                a1 = fmaf(x4[q].y, c4.y, a1);
                a2 = fmaf(x4[q].z, c4.z, a2);
                a3 = fmaf(x4[q].w, c4.w, a3);
            }
            v[j] = fmaf(S2LOG2, (a0 + a1) + (a2 + a3), -sB[j]);
        }
        float m0 = v[0], m1 = v[1], m2 = v[2], m3 = v[3];
#pragma unroll
        for (int j = 4; j < KC; j += 4) {
            m0 = fmaxf(m0, v[j]);   m1 = fmaxf(m1, v[j+1]);
            m2 = fmaxf(m2, v[j+2]); m3 = fmaxf(m3, v[j+3]);
        }
        float vmax = fmaxf(fmaxf(m0, m1), fmaxf(m2, m3));
        if (insm) {
#pragma unroll
            for (int q = 0; q < 8; q++)
                *(float4*)&smrows[s0 * CPAD + 4 * q] =
                    make_float4(v[4*q]-vmax, v[4*q+1]-vmax, v[4*q+2]-vmax, v[4*q+3]-vmax);
        } else {
            float4* gr = (float4*)(grow_base + (size_t)s0 * KC);
#pragma unroll
            for (int q = 0; q < 8; q++)
                gr[q] = make_float4(v[4*q]-vmax, v[4*q+1]-vmax, v[4*q+2]-vmax, v[4*q+3]-vmax);
        }
    }
    __syncthreads();

    const float log2_mK = __log2f((float)m * (1.0f / KC));
    const float inv_m   = 1.0f / (float)m;

    float Greg = 0.f;    // this lane's dual G[lane] (redundant, identical across warps)

    // ---------------- Phase B: 50 Sinkhorn passes + 1 histogram pass
    // Per sample: t_j = G_j + r_ij; w = softmax_j(t); A_j += w_j.
    // G update: G_j += log2(m/K) - log2(sum_i w_ij). Final: hist = W / sum(W).
    // One barrier per pass: Wp double-buffered by parity; combine done by ALL
    // warps redundantly (identical results), Gs rewritten redundantly.
#define PASS_LOOP(LOADR)                                                        \
    for (int pass = 0; pass <= ITERS; pass++) {                                 \
        float A[KC];                                                            \
        _Pragma("unroll") for (int j = 0; j < KC; j++) A[j] = 0.f;              \
        for (int s = tid; s < m; s += NTHREADS) {                               \
            float t[KC];                                                        \
            _Pragma("unroll") for (int q = 0; q < 8; q++) {                     \
                float4 g4 = *(const float4*)&Gs[4 * q];                         \
                float4 r4 = LOADR(s, q);                                        \
                t[4*q]   = g4.x + r4.x; t[4*q+1] = g4.y + r4.y;                 \
                t[4*q+2] = g4.z + r4.z; t[4*q+3] = g4.w + r4.w;                 \
            }                                                                   \
            float m0 = t[0], m1 = t[1], m2 = t[2], m3 = t[3];                   \
            _Pragma("unroll") for (int j = 4; j < KC; j += 4) {                 \
                m0 = fmaxf(m0, t[j]);   m1 = fmaxf(m1, t[j+1]);                 \
                m2 = fmaxf(m2, t[j+2]); m3 = fmaxf(m3, t[j+3]);                 \
            }                                                                   \
            float mx = fmaxf(fmaxf(m0, m1), fmaxf(m2, m3));                     \
            float s0 = 0.f, s1 = 0.f, s2 = 0.f, s3 = 0.f;                       \
            _Pragma("unroll") for (int j = 0; j < KC; j += 4) {                 \
                float e0 = ex2f(t[j]   - mx);                                   \
                float e1 = ex2f(t[j+1] - mx);                                   \
                float e2 = ex2f(t[j+2] - mx);                                   \
                float e3 = ex2f(t[j+3] - mx);                                   \
                t[j] = e0; t[j+1] = e1; t[j+2] = e2; t[j+3] = e3;               \
                s0 += e0; s1 += e1; s2 += e2; s3 += e3;                         \
            }                                                                   \
            float inv = rcpf((s0 + s1) + (s2 + s3));                            \
            _Pragma("unroll") for (int j = 0; j < KC; j++)                      \
                A[j] = fmaf(t[j], inv, A[j]);                                   \
        }                                                                       \
        /* tree-halving cross-lane reduce: lane l ends with column-l sum */     \
        _Pragma("unroll") for (int off = 16; off; off >>= 1) {                  \
            bool hi = (lane & off) != 0;                                        \
            _Pragma("unroll") for (int i = 0; i < off; i++) {                   \
                float send = hi ? A[i] : A[i + off];                            \
                float recv = __shfl_xor_sync(0xffffffffu, send, off);           \
                float keep = hi ? A[i + off] : A[i];                            \
                A[i] = keep + recv;                                             \
            }                                                                   \
        }                                                                       \
        float* wpb = Wp + (pass & 1) * (NWARPS * KC);                           \
        wpb[warp * KC + lane] = A[0];                                           \
        __syncthreads();                                                        \
        /* every warp redundantly combines + updates duals (identical bits) */  \
        float w = 0.f;                                                          \
        _Pragma("unroll") for (int k = 0; k < NWARPS; k++)                      \
            w += wpb[k * KC + lane];                                            \
        if (pass < ITERS) {                                                     \
            Greg = Greg + log2_mK - __log2f(fmaxf(w, 1e-38f));                  \
            Gs[lane] = Greg;                                                    \
            __syncwarp();                                                       \
        } else if (warp == 0) {                                                 \
            float u = w * inv_m;                                                \
            float ssum = warpAllSum(u) + 1e-12f;                                \
            out[b * KC + lane] = u / ssum;                                      \
        }                                                                       \
    }

#define LOADR_S(ii, q) (*(const float4*)&smrows[(ii) * CPAD + 4 * (q)])
#define LOADR_G(ii, q) (__ldg((const float4*)(grow_base + (size_t)(ii) * KC) + (q)))

    if (insm) {
        PASS_LOOP(LOADR_S)
    } else {
        PASS_LOOP(LOADR_G)
    }
#undef PASS_LOOP
#undef LOADR_S
#undef LOADR_G
}

extern "C" void kernel_launch(void* const* d_in, const int* in_sizes, int n_in,
                              void* d_out, int out_size) {
    const float* X    = (const float*)d_in[0];
    const float* cb   = (const float*)d_in[1];
    const int*   bidx = (const int*)d_in[2];
    float*       out  = (float*)d_out;

    int N = in_sizes[2];
    int S = in_sizes[0] / (N * DD);
    int B = out_size / KC;

    cudaFuncSetAttribute(sinkhorn_hist_kernel,
                         cudaFuncAttributeMaxDynamicSharedMemorySize, SMEM_BYTES);
    sinkhorn_hist_kernel<<<B, NTHREADS, SMEM_BYTES>>>(X, cb, bidx, out, N, S);
}

// round 5
// speedup vs baseline: 1.5961x; 1.0038x over previous
#include <cuda_runtime.h>
#include <cstdint>

#define NTHREADS 512
#define NWARPS   16
#define KC       32
#define DD       64
#define CPAD     36            // padded row stride (floats): conflict-free LDS.128
#define MAX_M    1520          // rows held in SMEM
#define ITERS    50
// s = (1/eps)*log2(e) = 10 * 1.4426950408889634
#define SLOG2    14.426950408889634f
#define S2LOG2   28.853900817779268f

// SMEM (floats): rows[MAX_M*36] | cbS[32*64] | sB[32] | Gs[32] | Wp[2][16][32] | rng
#define ROWS_F   (MAX_M*CPAD)
#define SMEM_FLOATS (ROWS_F + KC*DD + KC + KC + 2*NWARPS*KC + 8)
#define SMEM_BYTES  (SMEM_FLOATS*4)

// DRAM fallback scratch (400000 samples * 32 cols) — statically allocated.
__device__ float g_cscratch[12800000u];

__device__ __forceinline__ float ex2f(float x) {
    float y; asm("ex2.approx.ftz.f32 %0, %1;" : "=f"(y) : "f"(x)); return y;
}
__device__ __forceinline__ float rcpf(float x) {
    float y; asm("rcp.approx.ftz.f32 %0, %1;" : "=f"(y) : "f"(x)); return y;
}
__device__ __forceinline__ uint32_t smem_u32(const void* p) {
    uint32_t a;
    asm("{ .reg .u64 t; cvta.to.shared.u64 t, %1; cvt.u32.u64 %0, t; }" : "=r"(a) : "l"(p));
    return a;
}
// volatile LDS.128 — blocks ptxas from hoisting G into 32 live registers
__device__ __forceinline__ float4 lds128v(uint32_t a) {
    float4 v;
    asm volatile("ld.shared.v4.f32 {%0,%1,%2,%3}, [%4];"
                 : "=f"(v.x), "=f"(v.y), "=f"(v.z), "=f"(v.w) : "r"(a));
    return v;
}
__device__ __forceinline__ float warpAllSum(float v) {
#pragma unroll
    for (int off = 16; off; off >>= 1) v += __shfl_xor_sync(0xffffffffu, v, off);
    return v;
}
__device__ __forceinline__ int lower_bound_dev(const int* __restrict__ a, int n, int key) {
    int lo = 0, hi = n;
    while (lo < hi) { int mid = (lo + hi) >> 1; if (__ldg(a + mid) < key) lo = mid + 1; else hi = mid; }
    return lo;
}

extern "C" __global__ void __launch_bounds__(NTHREADS, 1)
sinkhorn_hist_kernel(const float* __restrict__ X, const float* __restrict__ cb,
                     const int* __restrict__ bidx, float* __restrict__ out,
                     int N, int S, int B) {
    extern __shared__ float sm[];
    float* smrows = sm;                       // [MAX_M][36]
    float* cbS    = sm + ROWS_F;              // [32][64]
    float* sB     = cbS + KC * DD;            // s*||cb_j||^2
    float* Gs     = sB + KC;                  // duals (log2 domain)
    float* Wp     = Gs + KC;                  // [2][16][32] parity-buffered partials
    int*   rng    = (int*)(Wp + 2 * NWARPS * KC);

    const int tid  = threadIdx.x;
    const int lane = tid & 31;
    const int warp = tid >> 5;
    const uint32_t gsa = smem_u32(Gs);

    // stage codebook once (persistent CTA)
    for (int i = tid; i < KC * DD; i += NTHREADS) cbS[i] = __ldg(cb + i);
    if (tid < KC) {
        float s = 0.f;
#pragma unroll
        for (int d = 0; d < DD; d++) { float v = __ldg(cb + tid * DD + d); s = fmaf(v, v, s); }
        sB[tid] = SLOG2 * s;
    }

    // ================= persistent loop over graphs =================
    for (int b = blockIdx.x; b < B; b += gridDim.x) {
        if (tid == 0) {
            rng[0] = lower_bound_dev(bidx, N, b);
            rng[1] = lower_bound_dev(bidx, N, b + 1);
        }
        if (tid < KC) Gs[tid] = 0.f;
        __syncthreads();

        const int lo = rng[0];
        const int n  = rng[1] - rng[0];
        const int m  = n * S;

        if (n == 0) { if (tid < KC) out[b * KC + tid] = 1.0f / KC; continue; }

        const bool insm = (m <= MAX_M);
        float* grow_base = g_cscratch + (size_t)(lo * S) * KC;

        // ---- Phase A: r_ij = s*(v_j - vmax_i), v_j = 2s*(x.cb_j) - s*||cb_j||^2
        // (||x||^2 and the max(.,0) clamp cancel in every softmax/LSE -> dropped)
        for (int s0 = tid; s0 < m; s0 += NTHREADS) {
            const float4* xr = (const float4*)(X + ((size_t)(lo * S + s0) << 6));
            float4 x4[16];
#pragma unroll
            for (int i = 0; i < 16; i++) x4[i] = __ldg(xr + i);
            float v[KC];
#pragma unroll
            for (int j = 0; j < KC; j++) {
                const float4* cbr = (const float4*)&cbS[j * DD];
                float a0 = 0.f, a1 = 0.f, a2 = 0.f, a3 = 0.f;
#pragma unroll
                for (int q = 0; q < 16; q++) {
                    float4 c4 = cbr[q];
                    a0 = fmaf(x4[q].x, c4.x, a0);
                    a1 = fmaf(x4[q].y, c4.y, a1);
                    a2 = fmaf(x4[q].z, c4.z, a2);
                    a3 = fmaf(x4[q].w, c4.w, a3);
                }
                v[j] = fmaf(S2LOG2, (a0 + a1) + (a2 + a3), -sB[j]);
            }
            float m0 = v[0], m1 = v[1], m2 = v[2], m3 = v[3];
#pragma unroll
            for (int j = 4; j < KC; j += 4) {
                m0 = fmaxf(m0, v[j]);   m1 = fmaxf(m1, v[j+1]);
                m2 = fmaxf(m2, v[j+2]); m3 = fmaxf(m3, v[j+3]);
            }
            float vmax = fmaxf(fmaxf(m0, m1), fmaxf(m2, m3));
            if (insm) {
#pragma unroll
                for (int q = 0; q < 8; q++)
                    *(float4*)&smrows[s0 * CPAD + 4 * q] =
                        make_float4(v[4*q]-vmax, v[4*q+1]-vmax, v[4*q+2]-vmax, v[4*q+3]-vmax);
            } else {
                float4* gr = (float4*)(grow_base + (size_t)s0 * KC);
#pragma unroll
                for (int q = 0; q < 8; q++)
                    gr[q] = make_float4(v[4*q]-vmax, v[4*q+1]-vmax, v[4*q+2]-vmax, v[4*q+3]-vmax);
            }
        }
        __syncthreads();

        const float log2_mK = __log2f((float)m * (1.0f / KC));
        const float inv_m   = 1.0f / (float)m;
        float Greg = 0.f;   // lane's dual (identical across warps)

        // ---- Phase B: 50 Sinkhorn passes + 1 histogram pass, ILP-2 rows ----
#define PASS_LOOP(LOADR)                                                        \
    for (int pass = 0; pass <= ITERS; pass++) {                                 \
        float A[KC];                                                            \
        _Pragma("unroll") for (int j = 0; j < KC; j++) A[j] = 0.f;              \
        for (int base = 0; base < m; base += 2 * NTHREADS) {                    \
            int sA = base + tid, sBn = sA + NTHREADS;                           \
            int iA = (sA < m) ? sA : 0;                                         \
            bool warpB = (base + (warp << 5) + NTHREADS) < m;                   \
            float tA[KC];                                                       \
            if (warpB) {                                                        \
                int iB = (sBn < m) ? sBn : 0;                                   \
                float tB[KC];                                                   \
                _Pragma("unroll") for (int q = 0; q < 8; q++) {                 \
                    float4 g4 = lds128v(gsa + (q << 4));                        \
                    float4 a4 = LOADR(iA, q);                                   \
                    float4 b4 = LOADR(iB, q);                                   \
                    tA[4*q]   = g4.x + a4.x; tA[4*q+1] = g4.y + a4.y;           \
                    tA[4*q+2] = g4.z + a4.z; tA[4*q+3] = g4.w + a4.w;           \
                    tB[4*q]   = g4.x + b4.x; tB[4*q+1] = g4.y + b4.y;           \
                    tB[4*q+2] = g4.z + b4.z; tB[4*q+3] = g4.w + b4.w;           \
                }                                                               \
                float a0 = tA[0], a1 = tA[1], a2 = tA[2], a3 = tA[3];           \
                float b0 = tB[0], b1 = tB[1], b2 = tB[2], b3 = tB[3];           \
                _Pragma("unroll") for (int j = 4; j < KC; j += 4) {             \
                    a0 = fmaxf(a0, tA[j]);   a1 = fmaxf(a1, tA[j+1]);           \
                    a2 = fmaxf(a2, tA[j+2]); a3 = fmaxf(a3, tA[j+3]);           \
                    b0 = fmaxf(b0, tB[j]);   b1 = fmaxf(b1, tB[j+1]);           \
                    b2 = fmaxf(b2, tB[j+2]); b3 = fmaxf(b3, tB[j+3]);           \
                }                                                               \
                float mxA = fmaxf(fmaxf(a0, a1), fmaxf(a2, a3));                \
                float mxB = fmaxf(fmaxf(b0, b1), fmaxf(b2, b3));                \
                float uA0 = 0.f, uA1 = 0.f, uA2 = 0.f, uA3 = 0.f;               \
                float uB0 = 0.f, uB1 = 0.f, uB2 = 0.f, uB3 = 0.f;               \
                _Pragma("unroll") for (int j = 0; j < KC; j += 4) {             \
                    float eA0 = ex2f(tA[j]   - mxA);                            \
                    float eA1 = ex2f(tA[j+1] - mxA);                            \
                    float eA2 = ex2f(tA[j+2] - mxA);                            \
                    float eA3 = ex2f(tA[j+3] - mxA);                            \
                    float eB0 = ex2f(tB[j]   - mxB);                            \
                    float eB1 = ex2f(tB[j+1] - mxB);                            \
                    float eB2 = ex2f(tB[j+2] - mxB);                            \
                    float eB3 = ex2f(tB[j+3] - mxB);                            \
                    tA[j] = eA0; tA[j+1] = eA1; tA[j+2] = eA2; tA[j+3] = eA3;   \
                    tB[j] = eB0; tB[j+1] = eB1; tB[j+2] = eB2; tB[j+3] = eB3;   \
                    uA0 += eA0; uA1 += eA1; uA2 += eA2; uA3 += eA3;             \
                    uB0 += eB0; uB1 += eB1; uB2 += eB2; uB3 += eB3;             \
                }                                                               \
                float invA = rcpf((uA0 + uA1) + (uA2 + uA3));                   \
                float invB = rcpf((uB0 + uB1) + (uB2 + uB3));                   \
                invA = (sA  < m) ? invA : 0.f;                                  \
                invB = (sBn < m) ? invB : 0.f;                                  \
                _Pragma("unroll") for (int j = 0; j < KC; j++) {                \
                    A[j] = fmaf(tA[j], invA, A[j]);                             \
                    A[j] = fmaf(tB[j], invB, A[j]);                             \
                }                                                               \
            } else {                                                            \
                _Pragma("unroll") for (int q = 0; q < 8; q++) {                 \
                    float4 g4 = lds128v(gsa + (q << 4));                        \
                    float4 a4 = LOADR(iA, q);                                   \
                    tA[4*q]   = g4.x + a4.x; tA[4*q+1] = g4.y + a4.y;           \
                    tA[4*q+2] = g4.z + a4.z; tA[4*q+3] = g4.w + a4.w;           \
                }                                                               \
                float a0 = tA[0], a1 = tA[1], a2 = tA[2], a3 = tA[3];           \
                _Pragma("unroll") for (int j = 4; j < KC; j += 4) {             \
                    a0 = fmaxf(a0, tA[j]);   a1 = fmaxf(a1, tA[j+1]);           \
                    a2 = fmaxf(a2, tA[j+2]); a3 = fmaxf(a3, tA[j+3]);           \
                }                                                               \
                float mxA = fmaxf(fmaxf(a0, a1), fmaxf(a2, a3));                \
                float uA0 = 0.f, uA1 = 0.f, uA2 = 0.f, uA3 = 0.f;               \
                _Pragma("unroll") for (int j = 0; j < KC; j += 4) {             \
                    float e0 = ex2f(tA[j]   - mxA);                             \
                    float e1 = ex2f(tA[j+1] - mxA);                             \
                    float e2 = ex2f(tA[j+2] - mxA);                             \
                    float e3 = ex2f(tA[j+3] - mxA);                             \
                    tA[j] = e0; tA[j+1] = e1; tA[j+2] = e2; tA[j+3] = e3;       \
                    uA0 += e0; uA1 += e1; uA2 += e2; uA3 += e3;                 \
                }                                                               \
                float invA = rcpf((uA0 + uA1) + (uA2 + uA3));                   \
                invA = (sA < m) ? invA : 0.f;                                   \
                _Pragma("unroll") for (int j = 0; j < KC; j++)                  \
                    A[j] = fmaf(tA[j], invA, A[j]);                             \
            }                                                                   \
        }                                                                       \
        /* tree-halving cross-lane reduce: lane l ends with column-l sum */     \
        _Pragma("unroll") for (int off = 16; off; off >>= 1) {                  \
            bool hi = (lane & off) != 0;                                        \
            _Pragma("unroll") for (int i = 0; i < off; i++) {                   \
                float send = hi ? A[i] : A[i + off];                            \
                float recv = __shfl_xor_sync(0xffffffffu, send, off);           \
                float keep = hi ? A[i + off] : A[i];                            \
                A[i] = keep + recv;                                             \
            }                                                                   \
        }                                                                       \
        float* wpb = Wp + (pass & 1) * (NWARPS * KC);                           \
        wpb[warp * KC + lane] = A[0];                                           \
        __syncthreads();                                                        \
        /* every warp redundantly combines + updates duals (identical bits) */  \
        float w = 0.f;                                                          \
        _Pragma("unroll") for (int k = 0; k < NWARPS; k++)                      \
            w += wpb[k * KC + lane];                                            \
        if (pass < ITERS) {                                                     \
            Greg = Greg + log2_mK - __log2f(fmaxf(w, 1e-38f));                  \
            Gs[lane] = Greg;                                                    \
            __syncwarp();                                                       \
        } else if (warp == 0) {                                                 \
            float u = w * inv_m;                                                \
            float ssum = warpAllSum(u) + 1e-12f;                                \
            out[b * KC + lane] = u / ssum;                                      \
        }                                                                       \
    }

#define LOADR_S(ii, q) (*(const float4*)&smrows[(ii) * CPAD + 4 * (q)])
#define LOADR_G(ii, q) (__ldg((const float4*)(grow_base + (size_t)(ii) * KC) + (q)))

        if (insm) {
            PASS_LOOP(LOADR_S)
        } else {
            PASS_LOOP(LOADR_G)
        }
#undef PASS_LOOP
#undef LOADR_S
#undef LOADR_G
    }
}

extern "C" void kernel_launch(void* const* d_in, const int* in_sizes, int n_in,
                              void* d_out, int out_size) {
    const float* X    = (const float*)d_in[0];
    const float* cb   = (const float*)d_in[1];
    const int*   bidx = (const int*)d_in[2];
    float*       out  = (float*)d_out;

    int N = in_sizes[2];
    int S = in_sizes[0] / (N * DD);
    int B = out_size / KC;

    int dev = 0, nsm = 148;
    cudaGetDevice(&dev);
    cudaDeviceGetAttribute(&nsm, cudaDevAttrMultiProcessorCount, dev);
    int grid = (B < nsm) ? B : nsm;

    cudaFuncSetAttribute(sinkhorn_hist_kernel,
                         cudaFuncAttributeMaxDynamicSharedMemorySize, SMEM_BYTES);
    sinkhorn_hist_kernel<<<grid, NTHREADS, SMEM_BYTES>>>(X, cb, bidx, out, N, S, B);
}

// round 7
// speedup vs baseline: 1.6025x; 1.0040x over previous
#include <cuda_runtime.h>
#include <cstdint>

#define NTHREADS 512
#define NWARPS   16
#define KC       32
#define DD       64
#define CPAD     36            // padded row stride (floats): conflict-free LDS.128
#define MAX_M    1500          // rows held in SMEM (mean 781, sd 56)
#define ITERS    50
// s = (1/eps)*log2(e) = 10 * 1.4426950408889634
#define SLOG2    14.426950408889634f
#define S2LOG2   28.853900817779268f

// SMEM (floats): rows[MAX_M*36] | cbS[32*64] | sB[32] | Gs[32] | Wp[2][16][32] | rng
#define ROWS_F   (MAX_M*CPAD)
#define SMEM_FLOATS (ROWS_F + KC*DD + KC + KC + 2*NWARPS*KC + 8)
#define SMEM_BYTES  (SMEM_FLOATS*4)

// DRAM fallback scratch (400000 samples * 32 cols) — statically allocated.
__device__ float g_cscratch[12800000u];

__device__ __forceinline__ float ex2f(float x) {
    float y; asm("ex2.approx.ftz.f32 %0, %1;" : "=f"(y) : "f"(x)); return y;
}
__device__ __forceinline__ float rcpf(float x) {
    float y; asm("rcp.approx.ftz.f32 %0, %1;" : "=f"(y) : "f"(x)); return y;
}
__device__ __forceinline__ float warpAllSum(float v) {
#pragma unroll
    for (int off = 16; off; off >>= 1) v += __shfl_xor_sync(0xffffffffu, v, off);
    return v;
}
__device__ __forceinline__ int lower_bound_dev(const int* __restrict__ a, int n, int key) {
    int lo = 0, hi = n;
    while (lo < hi) { int mid = (lo + hi) >> 1; if (__ldg(a + mid) < key) lo = mid + 1; else hi = mid; }
    return lo;
}

extern "C" __global__ void __launch_bounds__(NTHREADS, 1)
sinkhorn_hist_kernel(const float* __restrict__ X, const float* __restrict__ cb,
                     const int* __restrict__ bidx, float* __restrict__ out,
                     int N, int S, int B) {
    extern __shared__ float sm[];
    float* smrows = sm;                       // [MAX_M][36]
    float* cbS    = sm + ROWS_F;              // [32][64]
    float* sB     = cbS + KC * DD;            // s*||cb_j||^2
    float* Gs     = sB + KC;                  // duals staging (log2 domain)
    float* Wp     = Gs + KC;                  // [2][16][32] parity-buffered partials
    int*   rng    = (int*)(Wp + 2 * NWARPS * KC);

    const int tid  = threadIdx.x;
    const int lane = tid & 31;
    const int warp = tid >> 5;
    const int cidx = lane & 3;                // column group: cols 8*cidx .. +7
    const int sub  = lane >> 2;               // sample slot within 8-sample group
    const int hoff = cidx << 3;

    // stage codebook once (persistent CTA)
    for (int i = tid; i < KC * DD; i += NTHREADS) cbS[i] = __ldg(cb + i);
    if (tid < KC) {
        float s = 0.f;
#pragma unroll
        for (int d = 0; d < DD; d++) { float v = __ldg(cb + tid * DD + d); s = fmaf(v, v, s); }
        sB[tid] = SLOG2 * s;
    }

    // ================= persistent loop over graphs =================
    for (int b = blockIdx.x; b < B; b += gridDim.x) {
        if (tid == 0) {
            rng[0] = lower_bound_dev(bidx, N, b);
            rng[1] = lower_bound_dev(bidx, N, b + 1);
        }
        __syncthreads();

        const int lo = rng[0];
        const int n  = rng[1] - rng[0];
        const int m  = n * S;

        if (n == 0) {
            if (tid < KC) out[b * KC + tid] = 1.0f / KC;
            __syncthreads();
            continue;
        }

        const bool insm = (m <= MAX_M);
        float* grow_base = g_cscratch + (size_t)(lo * S) * KC;

        // ---- Phase A: r_ij = s*(v_j - vmax_i), v_j = 2s*(x.cb_j) - s*||cb_j||^2
        // (||x||^2 and the max(.,0) clamp cancel in every softmax/LSE -> dropped)
        for (int s0 = tid; s0 < m; s0 += NTHREADS) {
            const float4* xr = (const float4*)(X + ((size_t)(lo * S + s0) << 6));
            float4 x4[16];
#pragma unroll
            for (int i = 0; i < 16; i++) x4[i] = __ldg(xr + i);
            float v[KC];
#pragma unroll
            for (int j = 0; j < KC; j++) {
                const float4* cbr = (const float4*)&cbS[j * DD];
                float a0 = 0.f, a1 = 0.f, a2 = 0.f, a3 = 0.f;
#pragma unroll
                for (int q = 0; q < 16; q++) {
                    float4 c4 = cbr[q];
                    a0 = fmaf(x4[q].x, c4.x, a0);
                    a1 = fmaf(x4[q].y, c4.y, a1);
                    a2 = fmaf(x4[q].z, c4.z, a2);
                    a3 = fmaf(x4[q].w, c4.w, a3);
                }
                v[j] = fmaf(S2LOG2, (a0 + a1) + (a2 + a3), -sB[j]);
            }
            float m0 = v[0], m1 = v[1], m2 = v[2], m3 = v[3];
#pragma unroll
            for (int j = 4; j < KC; j += 4) {
                m0 = fmaxf(m0, v[j]);   m1 = fmaxf(m1, v[j+1]);
                m2 = fmaxf(m2, v[j+2]); m3 = fmaxf(m3, v[j+3]);
            }
            float vmax = fmaxf(fmaxf(m0, m1), fmaxf(m2, m3));
            if (insm) {
#pragma unroll
                for (int q = 0; q < 8; q++)
                    *(float4*)&smrows[s0 * CPAD + 4 * q] =
                        make_float4(v[4*q]-vmax, v[4*q+1]-vmax, v[4*q+2]-vmax, v[4*q+3]-vmax);
            } else {
                float4* gr = (float4*)(grow_base + (size_t)s0 * KC);
#pragma unroll
                for (int q = 0; q < 8; q++)
                    gr[q] = make_float4(v[4*q]-vmax, v[4*q+1]-vmax, v[4*q+2]-vmax, v[4*q+3]-vmax);
            }
        }
        __syncthreads();

        const float log2_mK = __log2f((float)m * (1.0f / KC));
        const float inv_m   = 1.0f / (float)m;
        const int   ngroups = (m + 7) >> 3;

        float G[8];                  // duals for this lane's 8 columns
#pragma unroll
        for (int k = 0; k < 8; k++) G[k] = 0.f;
        float Gcol = 0.f;            // master dual for column == lane

        // ---- Phase B: 50 Sinkhorn passes + 1 histogram pass ----
        // 4 lanes per sample, 8 cols per lane; softmax reduce = 2 bfly rounds.
#define GROUP_MATH(ROWI, OKV)                                                   \
        {                                                                       \
            float4 ra = LOADR(ROWI, hoff);                                      \
            float4 rb = LOADR(ROWI, hoff + 4);                                  \
            float t0 = G[0] + ra.x, t1 = G[1] + ra.y;                           \
            float t2 = G[2] + ra.z, t3 = G[3] + ra.w;                           \
            float t4 = G[4] + rb.x, t5 = G[5] + rb.y;                           \
            float t6 = G[6] + rb.z, t7 = G[7] + rb.w;                           \
            float mx = fmaxf(fmaxf(fmaxf(t0, t1), fmaxf(t2, t3)),               \
                             fmaxf(fmaxf(t4, t5), fmaxf(t6, t7)));              \
            mx = fmaxf(mx, __shfl_xor_sync(0xffffffffu, mx, 1));                \
            mx = fmaxf(mx, __shfl_xor_sync(0xffffffffu, mx, 2));                \
            float e0 = ex2f(t0 - mx), e1 = ex2f(t1 - mx);                       \
            float e2 = ex2f(t2 - mx), e3 = ex2f(t3 - mx);                       \
            float e4 = ex2f(t4 - mx), e5 = ex2f(t5 - mx);                       \
            float e6 = ex2f(t6 - mx), e7 = ex2f(t7 - mx);                       \
            float ssum = ((e0 + e1) + (e2 + e3)) + ((e4 + e5) + (e6 + e7));     \
            ssum += __shfl_xor_sync(0xffffffffu, ssum, 1);                      \
            ssum += __shfl_xor_sync(0xffffffffu, ssum, 2);                      \
            float inv = rcpf(ssum);                                             \
            inv = (OKV) ? inv : 0.f;                                            \
            A[0] = fmaf(e0, inv, A[0]); A[1] = fmaf(e1, inv, A[1]);             \
            A[2] = fmaf(e2, inv, A[2]); A[3] = fmaf(e3, inv, A[3]);             \
            A[4] = fmaf(e4, inv, A[4]); A[5] = fmaf(e5, inv, A[5]);             \
            A[6] = fmaf(e6, inv, A[6]); A[7] = fmaf(e7, inv, A[7]);             \
        }

#define PASS_LOOP                                                               \
    for (int pass = 0; pass <= ITERS; pass++) {                                 \
        float A[8];                                                             \
        _Pragma("unroll") for (int k = 0; k < 8; k++) A[k] = 0.f;               \
        int g0 = warp;                                                          \
        for (; g0 + NWARPS < ngroups; g0 += 2 * NWARPS) {                       \
            int r0 = (g0 << 3) + sub;             /* always valid */            \
            int r1 = ((g0 + NWARPS) << 3) + sub;                                \
            bool ok1 = r1 < m;                                                  \
            int i1 = ok1 ? r1 : 0;                                              \
            GROUP_MATH(r0, true)                                                \
            GROUP_MATH(i1, ok1)                                                 \
        }                                                                       \
        if (g0 < ngroups) {                                                     \
            int r0 = (g0 << 3) + sub;                                           \
            bool ok0 = r0 < m;                                                  \
            int i0 = ok0 ? r0 : 0;                                              \
            GROUP_MATH(i0, ok0)                                                 \
        }                                                                       \
        /* reduce A over the 8 sample-slots (lanes sharing cidx) */             \
        _Pragma("unroll") for (int off = 4; off <= 16; off <<= 1) {             \
            _Pragma("unroll") for (int k = 0; k < 8; k++)                       \
                A[k] += __shfl_xor_sync(0xffffffffu, A[k], off);                \
        }                                                                       \
        float* wpb = Wp + (pass & 1) * (NWARPS * KC);                           \
        if (lane < 4) {                                                         \
            *(float4*)&wpb[warp * KC + hoff]     =                              \
                make_float4(A[0], A[1], A[2], A[3]);                            \
            *(float4*)&wpb[warp * KC + hoff + 4] =                              \
                make_float4(A[4], A[5], A[6], A[7]);                            \
        }                                                                       \
        __syncthreads();                                                        \
        /* every warp redundantly combines (identical bits) */                  \
        float w = 0.f;                                                          \
        _Pragma("unroll") for (int k = 0; k < NWARPS; k++)                      \
            w += wpb[k * KC + lane];                                            \
        if (pass < ITERS) {                                                     \
            Gcol = Gcol + log2_mK - __log2f(fmaxf(w, 1e-38f));                  \
            Gs[lane] = Gcol;                                                    \
            __syncwarp();                                                       \
            float4 ga = *(const float4*)&Gs[hoff];                              \
            float4 gb = *(const float4*)&Gs[hoff + 4];                          \
            G[0] = ga.x; G[1] = ga.y; G[2] = ga.z; G[3] = ga.w;                 \
            G[4] = gb.x; G[5] = gb.y; G[6] = gb.z; G[7] = gb.w;                 \
        } else if (warp == 0) {                                                 \
            float u = w * inv_m;                                                \
            float ssum2 = warpAllSum(u) + 1e-12f;                               \
            out[b * KC + lane] = u / ssum2;                                     \
        }                                                                       \
    }

#define LOADR(ii, oo) (*(const float4*)&smrows[(ii) * CPAD + (oo)])
        if (insm) {
            PASS_LOOP
        }
#undef LOADR
#define LOADR(ii, oo) (__ldg((const float4*)(grow_base + (size_t)(ii) * KC + (oo))))
        if (!insm) {
            PASS_LOOP
        }
#undef LOADR
#undef PASS_LOOP
#undef GROUP_MATH
        __syncthreads();   // protect smrows/Gs/rng before next graph reuses them
    }
}

extern "C" void kernel_launch(void* const* d_in, const int* in_sizes, int n_in,
                              void* d_out, int out_size) {
    const float* X    = (const float*)d_in[0];
    const float* cb   = (const float*)d_in[1];
    const int*   bidx = (const int*)d_in[2];
    float*       out  = (float*)d_out;

    int N = in_sizes[2];
    int S = in_sizes[0] / (N * DD);
    int B = out_size / KC;

    int dev = 0, nsm = 148;
    cudaGetDevice(&dev);
    cudaDeviceGetAttribute(&nsm, cudaDevAttrMultiProcessorCount, dev);
    int grid = (B < nsm) ? B : nsm;

    cudaFuncSetAttribute(sinkhorn_hist_kernel,
                         cudaFuncAttributeMaxDynamicSharedMemorySize, SMEM_BYTES);
    sinkhorn_hist_kernel<<<grid, NTHREADS, SMEM_BYTES>>>(X, cb, bidx, out, N, S, B);
}

// round 8
// speedup vs baseline: 1.8043x; 1.1260x over previous
#include <cuda_runtime.h>
#include <cstdint>

#define NTHREADS 512
#define NWARPS   16
#define KC       32
#define DD       64
#define CPAD     36            // padded row stride (floats): conflict-free LDS.128
#define MAX_M    1500          // rows held in SMEM (mean 781, sd 56)
#define ITERS    50
#define TAU      2e-5f         // early-stop threshold on max|dG| (log2 units)
// s = (1/eps)*log2(e) = 10 * 1.4426950408889634
#define SLOG2    14.426950408889634f
#define S2LOG2   28.853900817779268f
#define NEGBIG   -1.0e30f

// SMEM (floats): rows[MAX_M*36] | cbS[32*64] | sB[32] | Gs[32] | Wp[2][16][32] | rng
#define ROWS_F   (MAX_M*CPAD)
#define SMEM_FLOATS (ROWS_F + KC*DD + KC + KC + 2*NWARPS*KC + 8)
#define SMEM_BYTES  (SMEM_FLOATS*4)

// DRAM fallback scratch: 400000*32 + per-graph pad 512*8*32 = 12,931,072 floats.
__device__ float g_cscratch[13100000u];

__device__ __forceinline__ float ex2f(float x) {
    float y; asm("ex2.approx.ftz.f32 %0, %1;" : "=f"(y) : "f"(x)); return y;
}
__device__ __forceinline__ float rcpf(float x) {
    float y; asm("rcp.approx.ftz.f32 %0, %1;" : "=f"(y) : "f"(x)); return y;
}
__device__ __forceinline__ float warpAllSum(float v) {
#pragma unroll
    for (int off = 16; off; off >>= 1) v += __shfl_xor_sync(0xffffffffu, v, off);
    return v;
}
__device__ __forceinline__ float warpAllMax(float v) {
#pragma unroll
    for (int off = 16; off; off >>= 1) v = fmaxf(v, __shfl_xor_sync(0xffffffffu, v, off));
    return v;
}
__device__ __forceinline__ int lower_bound_dev(const int* __restrict__ a, int n, int key) {
    int lo = 0, hi = n;
    while (lo < hi) { int mid = (lo + hi) >> 1; if (__ldg(a + mid) < key) lo = mid + 1; else hi = mid; }
    return lo;
}

extern "C" __global__ void __launch_bounds__(NTHREADS, 1)
sinkhorn_hist_kernel(const float* __restrict__ X, const float* __restrict__ cb,
                     const int* __restrict__ bidx, float* __restrict__ out,
                     int N, int S, int B) {
    extern __shared__ float sm[];
    float* smrows = sm;                       // [MAX_M][36]
    float* cbS    = sm + ROWS_F;              // [32][64]
    float* sB     = cbS + KC * DD;            // s*||cb_j||^2
    float* Gs     = sB + KC;                  // shifted duals staging (log2 domain)
    float* Wp     = Gs + KC;                  // [2][16][32] toggled partials
    int*   rng    = (int*)(Wp + 2 * NWARPS * KC);

    const int tid  = threadIdx.x;
    const int lane = tid & 31;
    const int warp = tid >> 5;
    const int cidx = lane & 3;                // column group: cols 8*cidx .. +7
    const int sub  = lane >> 2;               // sample slot within 8-sample group
    const int hoff = cidx << 3;

    // stage codebook once (persistent CTA)
    for (int i = tid; i < KC * DD; i += NTHREADS) cbS[i] = __ldg(cb + i);
    if (tid < KC) {
        float s = 0.f;
#pragma unroll
        for (int d = 0; d < DD; d++) { float v = __ldg(cb + tid * DD + d); s = fmaf(v, v, s); }
        sB[tid] = SLOG2 * s;
    }

    // ================= persistent loop over graphs =================
    for (int b = blockIdx.x; b < B; b += gridDim.x) {
        if (tid == 0) {
            rng[0] = lower_bound_dev(bidx, N, b);
            rng[1] = lower_bound_dev(bidx, N, b + 1);
        }
        __syncthreads();

        const int lo = rng[0];
        const int n  = rng[1] - rng[0];
        const int m  = n * S;

        if (n == 0) {
            if (tid < KC) out[b * KC + tid] = 1.0f / KC;
            __syncthreads();
            continue;
        }

        const int  ngroups = (m + 7) >> 3;
        const int  pad8    = ngroups << 3;
        const bool insm    = (pad8 <= MAX_M);
        float* grow_base = g_cscratch + ((size_t)(lo * S) + (size_t)b * 8) * KC;

        // ---- Phase A: r_ij = s*(v_j - vmax_i), v_j = 2s*(x.cb_j) - s*||cb_j||^2
        // (||x||^2 and the max(.,0) clamp cancel in every softmax/LSE -> dropped;
        //  per-row vmax shift makes max_j r_ij = 0, enabling the no-max Phase B)
        for (int s0 = tid; s0 < m; s0 += NTHREADS) {
            const float4* xr = (const float4*)(X + ((size_t)(lo * S + s0) << 6));
            float4 x4[16];
#pragma unroll
            for (int i = 0; i < 16; i++) x4[i] = __ldg(xr + i);
            float v[KC];
#pragma unroll
            for (int j = 0; j < KC; j++) {
                const float4* cbr = (const float4*)&cbS[j * DD];
                float a0 = 0.f, a1 = 0.f, a2 = 0.f, a3 = 0.f;
#pragma unroll
                for (int q = 0; q < 16; q++) {
                    float4 c4 = cbr[q];
                    a0 = fmaf(x4[q].x, c4.x, a0);
                    a1 = fmaf(x4[q].y, c4.y, a1);
                    a2 = fmaf(x4[q].z, c4.z, a2);
                    a3 = fmaf(x4[q].w, c4.w, a3);
                }
                v[j] = fmaf(S2LOG2, (a0 + a1) + (a2 + a3), -sB[j]);
            }
            float m0 = v[0], m1 = v[1], m2 = v[2], m3 = v[3];
#pragma unroll
            for (int j = 4; j < KC; j += 4) {
                m0 = fmaxf(m0, v[j]);   m1 = fmaxf(m1, v[j+1]);
                m2 = fmaxf(m2, v[j+2]); m3 = fmaxf(m3, v[j+3]);
            }
            float vmax = fmaxf(fmaxf(m0, m1), fmaxf(m2, m3));
            float* dst = insm ? &smrows[s0 * CPAD] : (grow_base + (size_t)s0 * KC);
#pragma unroll
            for (int q = 0; q < 8; q++)
                *(float4*)(dst + 4 * q) =
                    make_float4(v[4*q]-vmax, v[4*q+1]-vmax, v[4*q+2]-vmax, v[4*q+3]-vmax);
        }
        // pad rows [m, pad8) with NEGBIG -> e = 0, sum = 0 -> inv = 0 (no masks)
        for (int s0 = m + tid; s0 < pad8; s0 += NTHREADS) {
            float* dst = insm ? &smrows[s0 * CPAD] : (grow_base + (size_t)s0 * KC);
#pragma unroll
            for (int q = 0; q < 8; q++)
                *(float4*)(dst + 4 * q) = make_float4(NEGBIG, NEGBIG, NEGBIG, NEGBIG);
        }
        __syncthreads();

        const float log2_mK = __log2f((float)m * (1.0f / KC));
        const float inv_m   = 1.0f / (float)m;

        float G[8];                  // shifted duals for this lane's 8 columns
#pragma unroll
        for (int k = 0; k < 8; k++) G[k] = 0.f;
        float Gcol = 0.f;            // absolute dual for column == lane
        int   pb   = 0;              // Wp toggle

        // ---- Phase B: Sinkhorn passes (early-stoppable) + 1 histogram pass ----
        // 4 lanes/sample, 8 cols/lane; no row max: t = G' + r <= 0 always.
#define GROUP_MATH(P)                                                           \
        {                                                                       \
            float4 ra = LOADV((P));                                             \
            float4 rb = LOADV((P) + 4);                                         \
            float t0 = G[0] + ra.x, t1 = G[1] + ra.y;                           \
            float t2 = G[2] + ra.z, t3 = G[3] + ra.w;                           \
            float t4 = G[4] + rb.x, t5 = G[5] + rb.y;                           \
            float t6 = G[6] + rb.z, t7 = G[7] + rb.w;                           \
            float e0 = ex2f(t0), e1 = ex2f(t1), e2 = ex2f(t2), e3 = ex2f(t3);   \
            float e4 = ex2f(t4), e5 = ex2f(t5), e6 = ex2f(t6), e7 = ex2f(t7);   \
            float ssum = ((e0 + e1) + (e2 + e3)) + ((e4 + e5) + (e6 + e7));     \
            ssum += __shfl_xor_sync(0xffffffffu, ssum, 1);                      \
            ssum += __shfl_xor_sync(0xffffffffu, ssum, 2);                      \
            float inv = (ssum > 0.f) ? rcpf(ssum) : 0.f;                        \
            A[0] = fmaf(e0, inv, A[0]); A[1] = fmaf(e1, inv, A[1]);             \
            A[2] = fmaf(e2, inv, A[2]); A[3] = fmaf(e3, inv, A[3]);             \
            A[4] = fmaf(e4, inv, A[4]); A[5] = fmaf(e5, inv, A[5]);             \
            A[6] = fmaf(e6, inv, A[6]); A[7] = fmaf(e7, inv, A[7]);             \
        }

#define PASS_LOOP(ROWBASE, RSTRIDE)                                             \
    for (int pass = 0; pass <= ITERS; pass++) {                                 \
        float A[8];                                                             \
        _Pragma("unroll") for (int k = 0; k < 8; k++) A[k] = 0.f;               \
        const float* p = (ROWBASE) + (warp * 8 + sub) * (RSTRIDE) + hoff;       \
        const int step1 = NWARPS * 8 * (RSTRIDE);                               \
        int g = warp;                                                           \
        for (; g + NWARPS < ngroups; g += 2 * NWARPS) {                         \
            GROUP_MATH(p)                                                       \
            GROUP_MATH(p + step1)                                               \
            p += 2 * step1;                                                     \
        }                                                                       \
        if (g < ngroups) GROUP_MATH(p)                                          \
        /* reduce A over the 8 sample-slots (lanes sharing cidx) */             \
        _Pragma("unroll") for (int off = 4; off <= 16; off <<= 1) {             \
            _Pragma("unroll") for (int k = 0; k < 8; k++)                       \
                A[k] += __shfl_xor_sync(0xffffffffu, A[k], off);                \
        }                                                                       \
        float* wpb = Wp + pb * (NWARPS * KC);                                   \
        pb ^= 1;                                                                \
        if (lane < 4) {                                                         \
            *(float4*)&wpb[warp * KC + hoff]     =                              \
                make_float4(A[0], A[1], A[2], A[3]);                            \
            *(float4*)&wpb[warp * KC + hoff + 4] =                              \
                make_float4(A[4], A[5], A[6], A[7]);                            \
        }                                                                       \
        __syncthreads();                                                        \
        /* every warp redundantly combines (identical bits) */                  \
        float w = 0.f;                                                          \
        _Pragma("unroll") for (int k = 0; k < NWARPS; k++)                      \
            w += wpb[k * KC + lane];                                            \
        if (pass < ITERS) {                                                     \
            float dG = log2_mK - __log2f(fmaxf(w, 1e-38f));                     \
            Gcol += dG;                                                         \
            float mx = warpAllMax(Gcol);                                        \
            Gs[lane] = Gcol - mx;                                               \
            __syncwarp();                                                       \
            float4 ga = *(const float4*)&Gs[hoff];                              \
            float4 gb = *(const float4*)&Gs[hoff + 4];                          \
            G[0] = ga.x; G[1] = ga.y; G[2] = ga.z; G[3] = ga.w;                 \
            G[4] = gb.x; G[5] = gb.y; G[6] = gb.z; G[7] = gb.w;                 \
            float ad = warpAllMax(fabsf(dG));                                   \
            if (pass >= 10 && ad < TAU) pass = ITERS - 1; /* -> hist pass */    \
        } else if (warp == 0) {                                                 \
            float u = w * inv_m;                                                \
            float ssum2 = warpAllSum(u) + 1e-12f;                               \
            out[b * KC + lane] = u / ssum2;                                     \
        }                                                                       \
    }

#define LOADV(pp) (*(const float4*)(pp))
        if (insm) {
            PASS_LOOP(smrows, CPAD)
        }
#undef LOADV
#define LOADV(pp) (__ldg((const float4*)(pp)))
        if (!insm) {
            PASS_LOOP(grow_base, KC)
        }
#undef LOADV
#undef PASS_LOOP
#undef GROUP_MATH
        __syncthreads();   // protect smrows/Gs/rng before next graph reuses them
    }
}

extern "C" void kernel_launch(void* const* d_in, const int* in_sizes, int n_in,
                              void* d_out, int out_size) {
    const float* X    = (const float*)d_in[0];
    const float* cb   = (const float*)d_in[1];
    const int*   bidx = (const int*)d_in[2];
    float*       out  = (float*)d_out;

    int N = in_sizes[2];
    int S = in_sizes[0] / (N * DD);
    int B = out_size / KC;

    int dev = 0, nsm = 148;
    cudaGetDevice(&dev);
    cudaDeviceGetAttribute(&nsm, cudaDevAttrMultiProcessorCount, dev);
    int grid = (B < nsm) ? B : nsm;

    cudaFuncSetAttribute(sinkhorn_hist_kernel,
                         cudaFuncAttributeMaxDynamicSharedMemorySize, SMEM_BYTES);
    sinkhorn_hist_kernel<<<grid, NTHREADS, SMEM_BYTES>>>(X, cb, bidx, out, N, S, B);
}